// round 15
// baseline (speedup 1.0000x reference)
#include <cuda_runtime.h>
#include <cstdint>
#include <cfloat>

// RandomProjectionQuantizer (R14):
//   xp = x @ P    (normalization skipped: positive row scale preserves argmax)
//   out[i] = (float) argmax_j xp_i . CB_j      <- FLOAT output
//
// R14: (a) K2 processes 2 row-pairs (4 rows) per thread -> 4 indep FFMA2
// chains, LDS amortized 2x; (b) proj split-D 4-way, 512 CTAs, batched
// 8-deep float4 loads (MLP=8). K3 + tie-break semantics unchanged.

#define THREADS      256
#define CHUNK        256
#define SPLITS       32
#define MAXN         16384
#define MAXV         8192
#define MAXD         512

// ---------------- scratch ----------------
__device__ __align__(16) float g_xp4[4 * MAXN * 16];    // 4 partial xp buffers
__device__ float g_pval[SPLITS * MAXN];                 // 2 MB
__device__ int   g_pidx[SPLITS * MAXN];                 // 2 MB

// ---------------- f32x2 helpers ----------------
__device__ __forceinline__ unsigned long long splat2(float x) {
    unsigned long long r; unsigned int b = __float_as_uint(x);
    asm("mov.b64 %0, {%1, %1};" : "=l"(r) : "r"(b));
    return r;
}
__device__ __forceinline__ unsigned long long fma2(unsigned long long a,
                                                   unsigned long long b,
                                                   unsigned long long c) {
    unsigned long long d;
    asm("fma.rn.f32x2 %0, %1, %2, %3;" : "=l"(d) : "l"(a), "l"(b), "l"(c));
    return d;
}
__device__ __forceinline__ unsigned long long add2(unsigned long long a,
                                                   unsigned long long b) {
    unsigned long long d;
    asm("add.rn.f32x2 %0, %1, %2;" : "=l"(d) : "l"(a), "l"(b));
    return d;
}

// ============================================================================
// K1 (R14): split-D 4-way projection. grid = (N/128, 4). 128 thr, 1 row each.
// CTA (b, s): rows [b*128, +128), dims [s*D/4, +D/4). P quarter in smem (8KB),
// staged once; x loads batched 8 float4 deep (MLP=8); P reads warp-uniform.
// Output: partial xp, pair-interleaved, into g_xp4 + s*N*16.
// Requires D % 128 == 0, D <= MAXD, N % 128 == 0.
// ============================================================================
__global__ __launch_bounds__(128)
void proj_split4(const float* __restrict__ x, const float* __restrict__ P,
                 int N, int D) {
    __shared__ __align__(16) float Ps[(MAXD / 4) * 16];   // 8 KB max

    const int t   = threadIdx.x;
    const int s   = blockIdx.y;                 // D-quarter
    const int Dq  = D >> 2;
    const int d0  = s * Dq;
    const int row = blockIdx.x * 128 + t;

    // stage this quarter of P (Dq x 16 floats), float4-coalesced
    const int np4 = (Dq * 16) >> 2;
    const float4* Pg = (const float4*)(P + (long long)d0 * 16);
    for (int i = t; i < np4; i += 128)
        ((float4*)Ps)[i] = Pg[i];
    __syncthreads();

    float acc[16];
#pragma unroll
    for (int i = 0; i < 16; i++) acc[i] = 0.0f;

    const float4* xr = (const float4*)(x + (long long)row * D + d0);
    const int nb = Dq >> 5;                     // batches of 8 float4 (32 dims)

    for (int b = 0; b < nb; b++) {
        float4 xa[8];
#pragma unroll
        for (int i = 0; i < 8; i++) xa[i] = xr[b * 8 + i];   // 8 LDG in flight
#pragma unroll
        for (int i = 0; i < 8; i++) {
#pragma unroll
            for (int u = 0; u < 4; u++) {
                float xv = (u == 0) ? xa[i].x : (u == 1) ? xa[i].y
                         : (u == 2) ? xa[i].z : xa[i].w;
                const int d = (b * 8 + i) * 4 + u;            // warp-uniform
                const float4* pr = (const float4*)&Ps[d * 16];
                float4 p0 = pr[0], p1 = pr[1], p2 = pr[2], p3 = pr[3];
                acc[0]  = fmaf(xv, p0.x, acc[0]);  acc[1]  = fmaf(xv, p0.y, acc[1]);
                acc[2]  = fmaf(xv, p0.z, acc[2]);  acc[3]  = fmaf(xv, p0.w, acc[3]);
                acc[4]  = fmaf(xv, p1.x, acc[4]);  acc[5]  = fmaf(xv, p1.y, acc[5]);
                acc[6]  = fmaf(xv, p1.z, acc[6]);  acc[7]  = fmaf(xv, p1.w, acc[7]);
                acc[8]  = fmaf(xv, p2.x, acc[8]);  acc[9]  = fmaf(xv, p2.y, acc[9]);
                acc[10] = fmaf(xv, p2.z, acc[10]); acc[11] = fmaf(xv, p2.w, acc[11]);
                acc[12] = fmaf(xv, p3.x, acc[12]); acc[13] = fmaf(xv, p3.y, acc[13]);
                acc[14] = fmaf(xv, p3.z, acc[14]); acc[15] = fmaf(xv, p3.w, acc[15]);
            }
        }
    }

    // pair-interleave into partial buffer s
    float* dst = g_xp4 + (long long)s * N * 16 + (row >> 1) * 32 + (row & 1);
#pragma unroll
    for (int k = 0; k < 16; k++) dst[2 * k] = acc[k];
}

// ============================================================================
// K2 (R14): split-K argmax, 2 row-pairs (4 rows) per thread, FFMA2.
// grid = (N/4 / 256, SPLITS). xp = sum of 4 partial buffers (lane-wise add2).
// ============================================================================
__global__ __launch_bounds__(THREADS)
void argmax_partial4(const float* __restrict__ CB, int N, int V) {
    __shared__ __align__(16) unsigned long long cbs[CHUNK][16];   // 32 KB

    const int t = threadIdx.x;
    const int code0 = blockIdx.y * CHUNK;

#pragma unroll 4
    for (int q = t; q < CHUNK * 16; q += THREADS) {
        float c = CB[(long long)(code0 + (q >> 4)) * 16 + (q & 15)];
        cbs[q >> 4][q & 15] = splat2(c);
    }

    // row quad rq -> row pairs 2rq, 2rq+1 (rows 4rq..4rq+3)
    const int rq = blockIdx.x * THREADS + t;
    const long long stride = (long long)N * 16;   // u64 elems per partial buffer /2... (floats)
    unsigned long long xp0[16], xp1[16];
    {
        const ulonglong2* A0 = (const ulonglong2*)(g_xp4 + (long long)(2 * rq) * 32);
        const ulonglong2* A1 = (const ulonglong2*)(g_xp4 + (long long)(2 * rq + 1) * 32);
#pragma unroll
        for (int i = 0; i < 8; i++) {
            ulonglong2 a = A0[i], b = *(const ulonglong2*)((const float*)(A0 + i) + stride);
            ulonglong2 c = *(const ulonglong2*)((const float*)(A0 + i) + 2 * stride);
            ulonglong2 d = *(const ulonglong2*)((const float*)(A0 + i) + 3 * stride);
            xp0[2 * i]     = add2(add2(a.x, b.x), add2(c.x, d.x));
            xp0[2 * i + 1] = add2(add2(a.y, b.y), add2(c.y, d.y));
            ulonglong2 a2 = A1[i], b2 = *(const ulonglong2*)((const float*)(A1 + i) + stride);
            ulonglong2 c2 = *(const ulonglong2*)((const float*)(A1 + i) + 2 * stride);
            ulonglong2 d2 = *(const ulonglong2*)((const float*)(A1 + i) + 3 * stride);
            xp1[2 * i]     = add2(add2(a2.x, b2.x), add2(c2.x, d2.x));
            xp1[2 * i + 1] = add2(add2(a2.y, b2.y), add2(c2.y, d2.y));
        }
    }

    __syncthreads();

    float best0 = -FLT_MAX, best1 = -FLT_MAX, best2 = -FLT_MAX, best3 = -FLT_MAX;
    int idx0 = 0, idx1 = 0, idx2 = 0, idx3 = 0;

#pragma unroll 2
    for (int j = 0; j < CHUNK; j++) {
        const ulonglong2* cp = (const ulonglong2*)&cbs[j][0];   // broadcast LDS.128
        unsigned long long a0 = 0ULL, b0 = 0ULL, a1 = 0ULL, b1 = 0ULL;  // 4 chains
#pragma unroll
        for (int i = 0; i < 8; i++) {
            ulonglong2 c = cp[i];
            a0 = fma2(xp0[2 * i],     c.x, a0);
            b0 = fma2(xp0[2 * i + 1], c.y, b0);
            a1 = fma2(xp1[2 * i],     c.x, a1);
            b1 = fma2(xp1[2 * i + 1], c.y, b1);
        }
        union { unsigned long long u; float f[2]; } s0, s1;
        s0.u = add2(a0, b0);                      // rows 4rq, 4rq+1
        s1.u = add2(a1, b1);                      // rows 4rq+2, 4rq+3
        if (s0.f[0] > best0) { best0 = s0.f[0]; idx0 = j; }   // strict >: first max
        if (s0.f[1] > best1) { best1 = s0.f[1]; idx1 = j; }
        if (s1.f[0] > best2) { best2 = s1.f[0]; idx2 = j; }
        if (s1.f[1] > best3) { best3 = s1.f[1]; idx3 = j; }
    }

    const long long off = (long long)blockIdx.y * N + (long long)rq * 4;
    g_pval[off]     = best0;  g_pidx[off]     = code0 + idx0;
    g_pval[off + 1] = best1;  g_pidx[off + 1] = code0 + idx1;
    g_pval[off + 2] = best2;  g_pidx[off + 2] = code0 + idx2;
    g_pval[off + 3] = best3;  g_pidx[off + 3] = code0 + idx3;
}

// ============================================================================
// K3: reduce partials; ascending split + strict > = global first-max. Float out.
// ============================================================================
__global__ __launch_bounds__(256)
void argmax_reduce(float* __restrict__ out, int N, int nsplit) {
    const int row = blockIdx.x * 256 + threadIdx.x;
    if (row >= N) return;
    float best = -FLT_MAX;
    int bi = 0;
    for (int s = 0; s < nsplit; s++) {
        float v = g_pval[(long long)s * N + row];
        if (v > best) { best = v; bi = g_pidx[(long long)s * N + row]; }
    }
    out[row] = (float)bi;
}

// ============================================================================
// Fallbacks (proven R10 kernels) for any other shape.
// ============================================================================
union SMemF {
    struct { __align__(16) float xs[128][33]; __align__(16) float Ps[32][16]; } p1;
    __align__(16) float cbs[CHUNK][16];
    struct { float sv[THREADS]; int si[THREADS]; } p3;
};

__global__ __launch_bounds__(THREADS)
void rpq_fused16(const float* __restrict__ x, const float* __restrict__ P,
                 const float* __restrict__ CB, float* __restrict__ out,
                 int N, int D, int V) {
    __shared__ SMemF sm;
    const int t = threadIdx.x;
    const int rl = t & 127;
    const int half = t >> 7;
    const int row0 = blockIdx.x * 128;

    float acc[16];
#pragma unroll
    for (int i = 0; i < 16; i++) acc[i] = 0.0f;

    const int nkc = (D + 31) >> 5;
    for (int kc = 0; kc < nkc; kc++) {
#pragma unroll
        for (int q = t; q < 128 * 32; q += THREADS) {
            int r = q >> 5, c = q & 31;
            int row = row0 + r, d = kc * 32 + c;
            sm.p1.xs[r][c] = (row < N && d < D) ? x[(long long)row * D + d] : 0.0f;
        }
#pragma unroll
        for (int q = t; q < 32 * 16; q += THREADS) {
            int k = q >> 4, i = q & 15;
            int d = kc * 32 + k;
            sm.p1.Ps[k][i] = (d < D) ? P[(long long)d * 16 + i] : 0.0f;
        }
        __syncthreads();
#pragma unroll 4
        for (int k = 0; k < 32; k++) {
            float xv = sm.p1.xs[rl][k];
            const float4* pr = (const float4*)&sm.p1.Ps[k][0];
#pragma unroll
            for (int i4 = 0; i4 < 4; i4++) {
                float4 p = pr[i4];
                acc[4 * i4]     = fmaf(xv, p.x, acc[4 * i4]);
                acc[4 * i4 + 1] = fmaf(xv, p.y, acc[4 * i4 + 1]);
                acc[4 * i4 + 2] = fmaf(xv, p.z, acc[4 * i4 + 2]);
                acc[4 * i4 + 3] = fmaf(xv, p.w, acc[4 * i4 + 3]);
            }
        }
        __syncthreads();
    }

    float best = -FLT_MAX; int bi = 0x7FFFFFFF;
    for (int c0 = 0; c0 < V; c0 += CHUNK) {
        const int cnt = (V - c0 < CHUNK) ? (V - c0) : CHUNK;
#pragma unroll
        for (int q = t; q < CHUNK * 16; q += THREADS) {
            int j = q >> 4, i = q & 15;
            sm.cbs[j][i] = (j < cnt) ? CB[(long long)(c0 + j) * 16 + i] : 0.0f;
        }
        __syncthreads();
        const int jbase = half * 128;
#pragma unroll 2
        for (int jj = 0; jj < 128; jj++) {
            const int j = jbase + jj;
            const float4* cb = (const float4*)&sm.cbs[j][0];
            float s0 = 0, s1 = 0, s2 = 0, s3 = 0;
#pragma unroll
            for (int i4 = 0; i4 < 4; i4++) {
                float4 c = cb[i4];
                s0 = fmaf(acc[4 * i4],     c.x, s0);
                s1 = fmaf(acc[4 * i4 + 1], c.y, s1);
                s2 = fmaf(acc[4 * i4 + 2], c.z, s2);
                s3 = fmaf(acc[4 * i4 + 3], c.w, s3);
            }
            float s = (s0 + s1) + (s2 + s3);
            if (c0 + j < V && s > best) { best = s; bi = c0 + j; }
        }
        __syncthreads();
    }

    sm.p3.sv[t] = best; sm.p3.si[t] = bi;
    __syncthreads();
    if (t < 128) {
        int row = row0 + t;
        if (row < N) {
            float slo = sm.p3.sv[t], shi = sm.p3.sv[t + 128];
            int   ilo = sm.p3.si[t], ihi = sm.p3.si[t + 128];
            int win = (shi > slo || (shi == slo && ihi < ilo)) ? ihi : ilo;
            out[row] = (float)win;
        }
    }
}

__global__ void rpq_generic(const float* __restrict__ x, const float* __restrict__ P,
                            const float* __restrict__ CB, float* __restrict__ out,
                            int N, int D, int V, int cbd) {
    int row = blockIdx.x * blockDim.x + threadIdx.x;
    if (row >= N) return;
    float acc[64];
    for (int i = 0; i < cbd; i++) acc[i] = 0.0f;
    for (int d = 0; d < D; d++) {
        float xv = x[(long long)row * D + d];
        for (int i = 0; i < cbd; i++) acc[i] = fmaf(xv, P[(long long)d * cbd + i], acc[i]);
    }
    float best = -FLT_MAX; int bi = 0;
    for (int j = 0; j < V; j++) {
        float s = 0.0f;
        for (int i = 0; i < cbd; i++) s = fmaf(acc[i], CB[(long long)j * cbd + i], s);
        if (s > best) { best = s; bi = j; }
    }
    out[row] = (float)bi;
}

// ============================================================================
extern "C" void kernel_launch(void* const* d_in, const int* in_sizes, int n_in,
                              void* d_out, int out_size) {
    const float* x  = (const float*)d_in[0];
    const float* P  = (n_in > 1) ? (const float*)d_in[1] : nullptr;
    const float* CB = (n_in > 2) ? (const float*)d_in[2] : nullptr;
    long long N = out_size, D = 512, CBD = 16, V = 8192;

    if (n_in >= 3 && out_size > 0) {
        int order[3] = {0, 1, 2};
        for (int a = 0; a < 2; a++)
            for (int b = a + 1; b < 3; b++)
                if ((long long)in_sizes[order[b]] > (long long)in_sizes[order[a]]) {
                    int tmp = order[a]; order[a] = order[b]; order[b] = tmp;
                }
        long long sx = in_sizes[order[0]];
        long long sc = in_sizes[order[1]];
        long long sp = in_sizes[order[2]];
        if (sx % N == 0) {
            long long d = sx / N;
            if (d > 0 && sp % d == 0) {
                long long cbd = sp / d;
                if (cbd > 0 && cbd <= 64 && sc % cbd == 0) {
                    long long v = sc / cbd;
                    if (v > 0 && d * cbd == sp && v * cbd == sc && N * d == sx) {
                        D = d; CBD = cbd; V = v;
                        x  = (const float*)d_in[order[0]];
                        CB = (const float*)d_in[order[1]];
                        P  = (const float*)d_in[order[2]];
                    }
                }
            }
        }
    }

    float* out = (float*)d_out;
    int Ni = (int)N, Di = (int)D, Vi = (int)V;

    const bool fast = (CBD == 16) && (Ni % 1024 == 0) && (Vi % CHUNK == 0) &&
                      (Di % 128 == 0) && (Di <= MAXD) && (Ni <= MAXN) &&
                      (Vi <= MAXV) && ((Vi / CHUNK) <= SPLITS) && (Vi >= CHUNK);

    if (fast) {
        const int nsplit   = Vi / CHUNK;
        const int rowquads = Ni / 4;
        proj_split4<<<dim3(Ni / 128, 4), 128>>>(x, P, Ni, Di);
        argmax_partial4<<<dim3(rowquads / THREADS, nsplit), THREADS>>>(CB, Ni, Vi);
        argmax_reduce<<<(Ni + 255) / 256, 256>>>(out, Ni, nsplit);
        return;
    }

    if (CBD == 16) {
        rpq_fused16<<<(Ni + 127) / 128, THREADS>>>(x, P, CB, out, Ni, Di, Vi);
    } else {
        rpq_generic<<<(Ni + 255) / 256, 256>>>(x, P, CB, out, Ni, Di, Vi, (int)CBD);
    }
}